// round 4
// baseline (speedup 1.0000x reference)
#include <cuda_runtime.h>
#include <cuda_bf16.h>

#define MAXN 50000
#define MAXE 800000
#define HDIM 96
#define HDIM2 192

// ---------------- scratch (device globals; no allocation allowed) ----------------
__device__ int   g_deg_in[MAXN];
__device__ int   g_deg_out[MAXN];
__device__ int   g_fill[MAXN];
__device__ int   g_rowptr[MAXN + 1];
__device__ int2  g_col2[MAXE];                 // {src, perm[src]} per edge (CSR by dst)
__device__ float g_norm_in[MAXN];
__device__ float g_norm_out[MAXN];
__device__ float g_Y[(size_t)MAXN * HDIM];     // x @ W1 (shared by both views)
__device__ float g_HB[(size_t)MAXN * HDIM2];   // layer-2 pre-aggregation features
__device__ float g_P[(size_t)MAXN * HDIM2];    // layer-1 post-PReLU (view-major halves)
__device__ float g_wsum[HDIM];
__device__ float g_bmsum;

// packed f32x2 FMA: acc = a * b + acc
__device__ __forceinline__ void fma_f32x2(unsigned long long& acc,
                                          unsigned long long a,
                                          unsigned long long b) {
    asm("fma.rn.f32x2 %0, %1, %2, %0;" : "+l"(acc) : "l"(a), "l"(b));
}

// ---------------- small setup kernels ----------------
__global__ void zero_kernel(int n) {
    int i = blockIdx.x * blockDim.x + threadIdx.x;
    if (i < n) { g_deg_in[i] = 0; g_deg_out[i] = 0; g_fill[i] = 0; }
}

__global__ void degree_kernel(const int* __restrict__ src, const int* __restrict__ dst, int e) {
    int i = blockIdx.x * blockDim.x + threadIdx.x;
    if (i < e) {
        atomicAdd(&g_deg_out[src[i]], 1);
        atomicAdd(&g_deg_in[dst[i]], 1);
    }
}

// Single-block exclusive scan of in-degrees -> rowptr; also norms + Wm row-sums.
__global__ void scan_kernel(int n, const float* __restrict__ Wm, const float* __restrict__ bm) {
    __shared__ int ssum[1024];
    int t = threadIdx.x;

    if (t < HDIM) {
        float s = 0.f;
        #pragma unroll 8
        for (int j = 0; j < HDIM; j++) s += Wm[t * HDIM + j];
        g_wsum[t] = s;
    }
    if (t == 0) {
        float s = 0.f;
        for (int j = 0; j < HDIM; j++) s += bm[j];
        g_bmsum = s;
    }

    int chunk = (n + 1023) / 1024;
    int beg = min(t * chunk, n);
    int end = min(beg + chunk, n);
    int s = 0;
    for (int i = beg; i < end; i++) s += g_deg_in[i];
    ssum[t] = s;
    __syncthreads();
    for (int off = 1; off < 1024; off <<= 1) {
        int v = (t >= off) ? ssum[t - off] : 0;
        __syncthreads();
        ssum[t] += v;
        __syncthreads();
    }
    int run = ssum[t] - s;
    for (int i = beg; i < end; i++) { g_rowptr[i] = run; run += g_deg_in[i]; }
    if (end == n) g_rowptr[n] = run;

    for (int i = beg; i < end; i++) {
        g_norm_in[i]  = rsqrtf((float)max(g_deg_in[i], 1));
        g_norm_out[i] = rsqrtf((float)max(g_deg_out[i], 1));
    }
}

__global__ void fill_kernel(const int* __restrict__ src, const int* __restrict__ dst,
                            const int* __restrict__ perm, int e) {
    int i = blockIdx.x * blockDim.x + threadIdx.x;
    if (i < e) {
        int d = dst[i];
        int s = src[i];
        int pos = g_rowptr[d] + atomicAdd(&g_fill[d], 1);
        g_col2[pos] = make_int2(s, perm[s]);
    }
}

// ---------------- f32x2 GEMM: C[m][0..95] = rowscale[m] * (A[m,:K] @ B[K,96]) ----------
// 128x96 tile, 256 threads, 8 rows x 6 cols per thread; occ 3 -> 444 slots (single
// wave for 391 blocks). blockIdx.y selects the view (A/C offset += 96).
__global__ __launch_bounds__(256, 3) void gemm96_kernel(
    const float* __restrict__ A, int lda,
    const float* __restrict__ B,
    float* __restrict__ C, int ldc,
    const float* __restrict__ rowscale,
    int M, int K)
{
    __shared__ __align__(16) float As[16][132];          // [kk][m], padded
    __shared__ unsigned long long Bs2[16][96];           // [kk][c] -> (b,b)
    int tid = threadIdx.x;
    int tx = tid & 15;   // col group: cols tx + 16*c
    int ty = tid >> 4;   // row group: rows ty*8 .. ty*8+7
    int row0 = blockIdx.x * 128;
    A += (size_t)blockIdx.y * HDIM;
    C += (size_t)blockIdx.y * HDIM;

    unsigned long long acc[4][6];
    #pragma unroll
    for (int r = 0; r < 4; r++)
        #pragma unroll
        for (int c = 0; c < 6; c++) acc[r][c] = 0ull;

    for (int k0 = 0; k0 < K; k0 += 16) {
        #pragma unroll
        for (int i = 0; i < 8; i++) {
            int idx = tid + i * 256;      // 0..2047
            int m = idx >> 4, kk = idx & 15;
            int gr = row0 + m, gk = k0 + kk;
            As[kk][m] = (gr < M && gk < K) ? A[(size_t)gr * lda + gk] : 0.f;
        }
        #pragma unroll
        for (int i = 0; i < 6; i++) {
            int idx = tid + i * 256;      // 0..1535
            int kk = idx / 96, c = idx - kk * 96;
            int gk = k0 + kk;
            float bv = (gk < K) ? B[gk * HDIM + c] : 0.f;
            unsigned int u = __float_as_uint(bv);
            Bs2[kk][c] = ((unsigned long long)u << 32) | u;
        }
        __syncthreads();
        #pragma unroll
        for (int kk = 0; kk < 16; kk++) {
            unsigned long long ap[4], bp[6];
            #pragma unroll
            for (int r = 0; r < 4; r++)
                ap[r] = *(const unsigned long long*)&As[kk][ty * 8 + 2 * r];
            #pragma unroll
            for (int c = 0; c < 6; c++)
                bp[c] = Bs2[kk][tx + 16 * c];
            #pragma unroll
            for (int r = 0; r < 4; r++)
                #pragma unroll
                for (int c = 0; c < 6; c++)
                    fma_f32x2(acc[r][c], ap[r], bp[c]);
        }
        __syncthreads();
    }

    #pragma unroll
    for (int r = 0; r < 4; r++) {
        int m0 = row0 + ty * 8 + 2 * r;
        #pragma unroll
        for (int h = 0; h < 2; h++) {
            int m = m0 + h;
            if (m < M) {
                float sc = rowscale ? rowscale[m] : 1.f;
                #pragma unroll
                for (int c = 0; c < 6; c++) {
                    unsigned int u = (unsigned int)(h ? (acc[r][c] >> 32)
                                                      : (acc[r][c] & 0xffffffffull));
                    C[(size_t)m * ldc + tx + 16 * c] = __uint_as_float(u) * sc;
                }
            }
        }
    }
}

// ---------------- layer-1 aggregation: gathers Y directly (dual view, half-warp each) --
// P[i][v*96 + c] = prelu( norm_in[i] * sum_{s in N(i)} norm_out[s] * Yrow(v,s)[c] + b1[c] )
__global__ __launch_bounds__(256) void spmm1_kernel(
    const float* __restrict__ Y, float* __restrict__ Pout,
    const float* __restrict__ b, const float* __restrict__ a, int n)
{
    int gw = (blockIdx.x * blockDim.x + threadIdx.x) >> 5;
    int lane = threadIdx.x & 31;
    if (gw >= n) return;
    int half = lane >> 4;        // 0: view1 (Y[s]), 1: view2 (Y[perm[s]])
    int l = lane & 15;

    int beg = g_rowptr[gw], end = g_rowptr[gw + 1];
    float2 acc0 = {0.f, 0.f}, acc1 = {0.f, 0.f}, acc2 = {0.f, 0.f};

    int e = beg;
    for (; e + 1 < end; e += 2) {
        int2 sp0 = g_col2[e], sp1 = g_col2[e + 1];
        float ns0 = g_norm_out[sp0.x], ns1 = g_norm_out[sp1.x];
        int s0 = half ? sp0.y : sp0.x;
        int s1 = half ? sp1.y : sp1.x;
        const float2* h0 = (const float2*)(Y + (size_t)s0 * HDIM);
        const float2* h1 = (const float2*)(Y + (size_t)s1 * HDIM);
        float2 u0 = h0[l], u1 = h0[l + 16], u2 = h0[l + 32];
        float2 v0 = h1[l], v1 = h1[l + 16], v2 = h1[l + 32];
        acc0.x += ns0 * u0.x + ns1 * v0.x; acc0.y += ns0 * u0.y + ns1 * v0.y;
        acc1.x += ns0 * u1.x + ns1 * v1.x; acc1.y += ns0 * u1.y + ns1 * v1.y;
        acc2.x += ns0 * u2.x + ns1 * v2.x; acc2.y += ns0 * u2.y + ns1 * v2.y;
    }
    if (e < end) {
        int2 sp0 = g_col2[e];
        float ns0 = g_norm_out[sp0.x];
        int s0 = half ? sp0.y : sp0.x;
        const float2* h0 = (const float2*)(Y + (size_t)s0 * HDIM);
        float2 u0 = h0[l], u1 = h0[l + 16], u2 = h0[l + 32];
        acc0.x += ns0 * u0.x; acc0.y += ns0 * u0.y;
        acc1.x += ns0 * u1.x; acc1.y += ns0 * u1.y;
        acc2.x += ns0 * u2.x; acc2.y += ns0 * u2.y;
    }

    float ni = g_norm_in[gw];
    float2* po = (float2*)(Pout + (size_t)gw * HDIM2);

    #pragma unroll
    for (int j = 0; j < 3; j++) {
        int idx = l + 16 * j;          // float2 index within the 48 of this view
        int c0 = 2 * idx;              // channel within view
        float2 acc = (j == 0) ? acc0 : (j == 1) ? acc1 : acc2;
        float h0 = acc.x * ni + b[c0];
        float h1 = acc.y * ni + b[c0 + 1];
        float z0 = (h0 >= 0.f) ? h0 : a[c0] * h0;
        float z1 = (h1 >= 0.f) ? h1 : a[c0 + 1] * h1;
        po[half * 48 + idx] = make_float2(z0, z1);
    }
}

// ---------------- layer-2 aggregation + PReLU + fused projection row-sum ---------------
__global__ __launch_bounds__(256) void spmm2_kernel(
    const float* __restrict__ Hin,
    const float* __restrict__ b, const float* __restrict__ a,
    float* __restrict__ out, int n)
{
    int gw = (blockIdx.x * blockDim.x + threadIdx.x) >> 5;
    int lane = threadIdx.x & 31;
    if (gw >= n) return;

    int beg = g_rowptr[gw], end = g_rowptr[gw + 1];
    float2 acc0 = {0.f, 0.f}, acc1 = {0.f, 0.f}, acc2 = {0.f, 0.f};

    int e = beg;
    for (; e + 1 < end; e += 2) {
        int s0 = g_col2[e].x, s1 = g_col2[e + 1].x;
        const float2* h0 = (const float2*)(Hin + (size_t)s0 * HDIM2);
        const float2* h1 = (const float2*)(Hin + (size_t)s1 * HDIM2);
        float2 u0 = h0[lane], u1 = h0[lane + 32], u2 = h0[lane + 64];
        float2 v0 = h1[lane], v1 = h1[lane + 32], v2 = h1[lane + 64];
        acc0.x += u0.x + v0.x; acc0.y += u0.y + v0.y;
        acc1.x += u1.x + v1.x; acc1.y += u1.y + v1.y;
        acc2.x += u2.x + v2.x; acc2.y += u2.y + v2.y;
    }
    if (e < end) {
        int s0 = g_col2[e].x;
        const float2* h0 = (const float2*)(Hin + (size_t)s0 * HDIM2);
        float2 u0 = h0[lane], u1 = h0[lane + 32], u2 = h0[lane + 64];
        acc0.x += u0.x; acc0.y += u0.y;
        acc1.x += u1.x; acc1.y += u1.y;
        acc2.x += u2.x; acc2.y += u2.y;
    }

    float ni = g_norm_in[gw];
    float s1 = 0.f, s2 = 0.f;

    #pragma unroll
    for (int j = 0; j < 3; j++) {
        int idx = lane + 32 * j;
        float2 acc = (j == 0) ? acc0 : (j == 1) ? acc1 : acc2;
        int v = idx >= 48;
        int c0 = 2 * idx - 96 * v;
        float h0 = acc.x * ni + b[c0];
        float h1 = acc.y * ni + b[c0 + 1];
        float z0 = (h0 >= 0.f) ? h0 : a[c0] * h0;
        float z1 = (h1 >= 0.f) ? h1 : a[c0 + 1] * h1;
        float contrib = z0 * g_wsum[c0] + z1 * g_wsum[c0 + 1];
        if (v) s2 += contrib; else s1 += contrib;
    }

    #pragma unroll
    for (int off = 16; off > 0; off >>= 1) {
        s1 += __shfl_xor_sync(0xffffffff, s1, off);
        s2 += __shfl_xor_sync(0xffffffff, s2, off);
    }
    if (lane == 0) {
        out[gw]     = s1 + g_bmsum;
        out[n + gw] = s2 + g_bmsum;
    }
}

// ---------------- launch ----------------
extern "C" void kernel_launch(void* const* d_in, const int* in_sizes, int n_in,
                              void* d_out, int out_size) {
    const float* x   = (const float*)d_in[0];
    const int*   src = (const int*)  d_in[1];
    const int*   dst = (const int*)  d_in[2];
    const int*   perm= (const int*)  d_in[3];
    const float* W1  = (const float*)d_in[4];
    const float* b1  = (const float*)d_in[5];
    const float* a1  = (const float*)d_in[6];
    const float* W2  = (const float*)d_in[7];
    const float* b2  = (const float*)d_in[8];
    const float* a2  = (const float*)d_in[9];
    const float* Wm  = (const float*)d_in[10];
    const float* bm  = (const float*)d_in[11];
    float* out = (float*)d_out;

    int E = in_sizes[1];
    int n = in_sizes[3];
    int F = in_sizes[0] / n;

    float *pY, *pHB, *pP, *pNormOut;
    cudaGetSymbolAddress((void**)&pY, g_Y);
    cudaGetSymbolAddress((void**)&pHB, g_HB);
    cudaGetSymbolAddress((void**)&pP, g_P);
    cudaGetSymbolAddress((void**)&pNormOut, g_norm_out);

    zero_kernel<<<(n + 255) / 256, 256>>>(n);                       // #1
    degree_kernel<<<(E + 255) / 256, 256>>>(src, dst, E);           // #2
    scan_kernel<<<1, 1024>>>(n, Wm, bm);                            // #3
    // Y = X @ W1 (shared by both views) — positioned 4th so ncu captures it
    gemm96_kernel<<<dim3((n + 127) / 128, 1), 256>>>(
        x, F, W1, pY, HDIM, nullptr, n, F);                         // #4
    fill_kernel<<<(E + 255) / 256, 256>>>(src, dst, perm, E);       // #5
    // layer-1 aggregation (dual view, direct gather from Y) + PReLU
    spmm1_kernel<<<(n + 7) / 8, 256>>>(pY, pP, b1, a1, n);          // #6
    // layer-2 GEMMs, both views in one launch, norm_out fused in epilogue
    gemm96_kernel<<<dim3((n + 127) / 128, 2), 256>>>(
        pP, HDIM2, W2, pHB, HDIM2, pNormOut, n, HDIM);              // #7
    // layer-2 aggregation + PReLU + fused projection row-sum
    spmm2_kernel<<<(n + 7) / 8, 256>>>(pHB, b2, a2, out, n);        // #8
}

// round 5
// speedup vs baseline: 1.6623x; 1.6623x over previous
#include <cuda_runtime.h>
#include <cuda_bf16.h>

#define MAXN 50000
#define MAXE 800000
#define HDIM 96
#define HDIM2 192

// ---------------- scratch (device globals; no allocation allowed) ----------------
__device__ int   g_deg_in[MAXN];
__device__ int   g_deg_out[MAXN];
__device__ int   g_fill[MAXN];
__device__ int   g_rowptr[MAXN + 1];
__device__ int2  g_col2[MAXE];                 // {src, perm[src]} per edge (CSR by dst)
__device__ float g_norm_in[MAXN];
__device__ float g_norm_out[MAXN];
__device__ float g_Y[(size_t)MAXN * HDIM];     // x @ W1 (shared by both views)
__device__ float g_HB[(size_t)MAXN * HDIM2];   // split-K scratch, then layer-2 features
__device__ float g_P[(size_t)MAXN * HDIM2];    // layer-1 post-PReLU (view-major halves)
__device__ float g_wsum[HDIM];
__device__ float g_bmsum;

// packed f32x2 FMA: acc = a * b + acc
__device__ __forceinline__ void fma_f32x2(unsigned long long& acc,
                                          unsigned long long a,
                                          unsigned long long b) {
    asm("fma.rn.f32x2 %0, %1, %2, %0;" : "+l"(acc) : "l"(a), "l"(b));
}
__device__ __forceinline__ unsigned long long dupf(float f) {
    unsigned int u = __float_as_uint(f);
    return ((unsigned long long)u << 32) | u;
}

// ---------------- small setup kernels ----------------
__global__ void zero_kernel(int n) {
    int i = blockIdx.x * blockDim.x + threadIdx.x;
    if (i < n) { g_deg_in[i] = 0; g_deg_out[i] = 0; g_fill[i] = 0; }
}

__global__ void degree_kernel(const int* __restrict__ src, const int* __restrict__ dst, int e) {
    int i = blockIdx.x * blockDim.x + threadIdx.x;
    if (i < e) {
        atomicAdd(&g_deg_out[src[i]], 1);
        atomicAdd(&g_deg_in[dst[i]], 1);
    }
}

// Single-block exclusive scan of in-degrees -> rowptr; also norms + Wm row-sums.
__global__ void scan_kernel(int n, const float* __restrict__ Wm, const float* __restrict__ bm) {
    __shared__ int ssum[1024];
    int t = threadIdx.x;

    if (t < HDIM) {
        float s = 0.f;
        #pragma unroll 8
        for (int j = 0; j < HDIM; j++) s += Wm[t * HDIM + j];
        g_wsum[t] = s;
    }
    if (t == 0) {
        float s = 0.f;
        for (int j = 0; j < HDIM; j++) s += bm[j];
        g_bmsum = s;
    }

    int chunk = (n + 1023) / 1024;
    int beg = min(t * chunk, n);
    int end = min(beg + chunk, n);
    int s = 0;
    for (int i = beg; i < end; i++) s += g_deg_in[i];
    ssum[t] = s;
    __syncthreads();
    for (int off = 1; off < 1024; off <<= 1) {
        int v = (t >= off) ? ssum[t - off] : 0;
        __syncthreads();
        ssum[t] += v;
        __syncthreads();
    }
    int run = ssum[t] - s;
    for (int i = beg; i < end; i++) { g_rowptr[i] = run; run += g_deg_in[i]; }
    if (end == n) g_rowptr[n] = run;

    for (int i = beg; i < end; i++) {
        g_norm_in[i]  = rsqrtf((float)max(g_deg_in[i], 1));
        g_norm_out[i] = rsqrtf((float)max(g_deg_out[i], 1));
    }
}

__global__ void fill_kernel(const int* __restrict__ src, const int* __restrict__ dst,
                            const int* __restrict__ perm, int e) {
    int i = blockIdx.x * blockDim.x + threadIdx.x;
    if (i < e) {
        int d = dst[i];
        int s = src[i];
        int pos = g_rowptr[d] + atomicAdd(&g_fill[d], 1);
        g_col2[pos] = make_int2(s, perm[s]);
    }
}

// ---------------- pipelined f32x2 GEMM: C[m][0..95] = rowscale[m]*(A[m,kBeg:kEnd] @ B) --
// 128x96 tile, 256 threads, 8 rows x 6 cols per thread, row-pair-packed accumulators.
// Double-buffered smem, register-staged LDG.128 prefetch, one sync per k-tile.
// splitK>0: blockIdx.y selects K-half (C0/C1). splitK==0: blockIdx.y selects view (+96 cols).
__global__ __launch_bounds__(256, 2) void gemm96_kernel(
    const float* __restrict__ A, int lda,
    const float* __restrict__ B,
    float* __restrict__ C0, float* __restrict__ C1, int ldc,
    const float* __restrict__ rowscale,
    int M, int K, int splitK)
{
    __shared__ __align__(16) float As[2][16][132];           // [buf][kk][m]
    __shared__ unsigned long long Bs2[2][16][96];            // [buf][kk][c] -> (b,b)

    int tid = threadIdx.x;
    int tx = tid & 15;          // cols tx + 16*c
    int ty = tid >> 4;          // rows ty*8 .. ty*8+7
    int row0 = blockIdx.x * 128;
    int y = blockIdx.y;

    const float* Ab; float* C; int kBeg, kEnd;
    const float* rs = rowscale;
    if (splitK > 0) {
        int kMid = min(splitK, K);
        Ab = A; C = y ? C1 : C0;
        kBeg = y ? kMid : 0; kEnd = y ? K : kMid;
    } else {
        Ab = A + y * HDIM; C = C0 + y * HDIM;
        kBeg = 0; kEnd = K;
    }

    // load-assignment constants
    int qa = tid & 3, ma = tid >> 2;           // A: float4 quad qa, rows ma / ma+64
    int rA0 = row0 + ma, rA1 = row0 + ma + 64;
    int bk0 = tid / 24, bc0 = tid % 24;        // B: (kk, float4-col)
    int bk1 = (tid + 256) / 24, bc1 = (tid + 256) % 24;

    float4 a0, a1, b0, b1;
    const float4 Z = make_float4(0.f, 0.f, 0.f, 0.f);

    auto ldg = [&](int k0) {
        int gk = k0 + 4 * qa;
        bool kok = (gk + 4 <= kEnd);
        a0 = (kok && rA0 < M) ? *(const float4*)&Ab[(size_t)rA0 * lda + gk] : Z;
        a1 = (kok && rA1 < M) ? *(const float4*)&Ab[(size_t)rA1 * lda + gk] : Z;
        int g0 = k0 + bk0;
        b0 = (g0 < kEnd) ? *(const float4*)&B[(size_t)g0 * HDIM + 4 * bc0] : Z;
        if (tid < 128) {
            int g1 = k0 + bk1;
            b1 = (g1 < kEnd) ? *(const float4*)&B[(size_t)g1 * HDIM + 4 * bc1] : Z;
        }
    };
    auto sts = [&](int s) {
        As[s][4 * qa + 0][ma] = a0.x; As[s][4 * qa + 1][ma] = a0.y;
        As[s][4 * qa + 2][ma] = a0.z; As[s][4 * qa + 3][ma] = a0.w;
        As[s][4 * qa + 0][ma + 64] = a1.x; As[s][4 * qa + 1][ma + 64] = a1.y;
        As[s][4 * qa + 2][ma + 64] = a1.z; As[s][4 * qa + 3][ma + 64] = a1.w;
        Bs2[s][bk0][4 * bc0 + 0] = dupf(b0.x); Bs2[s][bk0][4 * bc0 + 1] = dupf(b0.y);
        Bs2[s][bk0][4 * bc0 + 2] = dupf(b0.z); Bs2[s][bk0][4 * bc0 + 3] = dupf(b0.w);
        if (tid < 128) {
            Bs2[s][bk1][4 * bc1 + 0] = dupf(b1.x); Bs2[s][bk1][4 * bc1 + 1] = dupf(b1.y);
            Bs2[s][bk1][4 * bc1 + 2] = dupf(b1.z); Bs2[s][bk1][4 * bc1 + 3] = dupf(b1.w);
        }
    };

    unsigned long long acc[4][6];
    #pragma unroll
    for (int r = 0; r < 4; r++)
        #pragma unroll
        for (int c = 0; c < 6; c++) acc[r][c] = 0ull;

    int nk = (kEnd - kBeg + 15) >> 4;
    ldg(kBeg);
    sts(0);
    for (int i = 0; i < nk; i++) {
        __syncthreads();
        if (i + 1 < nk) ldg(kBeg + (i + 1) * 16);
        int s = i & 1;
        #pragma unroll
        for (int kk = 0; kk < 16; kk++) {
            ulonglong2 apl = *(const ulonglong2*)&As[s][kk][ty * 8];
            ulonglong2 aph = *(const ulonglong2*)&As[s][kk][ty * 8 + 4];
            unsigned long long ap[4] = {apl.x, apl.y, aph.x, aph.y};
            unsigned long long bp[6];
            #pragma unroll
            for (int c = 0; c < 6; c++) bp[c] = Bs2[s][kk][tx + 16 * c];
            #pragma unroll
            for (int r = 0; r < 4; r++)
                #pragma unroll
                for (int c = 0; c < 6; c++)
                    fma_f32x2(acc[r][c], ap[r], bp[c]);
        }
        if (i + 1 < nk) sts((i + 1) & 1);
    }

    bool doScale = (rs != nullptr) && (splitK == 0);
    #pragma unroll
    for (int r = 0; r < 4; r++) {
        int m0 = row0 + ty * 8 + 2 * r;
        #pragma unroll
        for (int h = 0; h < 2; h++) {
            int m = m0 + h;
            if (m < M) {
                float sc = doScale ? rs[m] : 1.f;
                #pragma unroll
                for (int c = 0; c < 6; c++) {
                    unsigned int u = (unsigned int)(h ? (acc[r][c] >> 32)
                                                      : (acc[r][c] & 0xffffffffull));
                    C[(size_t)m * ldc + tx + 16 * c] = __uint_as_float(u) * sc;
                }
            }
        }
    }
}

// Y += split-K partial (float4 vectorized)
__global__ void add_kernel(float* __restrict__ dst, const float* __restrict__ srcp, int n4) {
    int i = blockIdx.x * blockDim.x + threadIdx.x;
    if (i < n4) {
        float4 a = ((const float4*)dst)[i];
        float4 b = ((const float4*)srcp)[i];
        a.x += b.x; a.y += b.y; a.z += b.z; a.w += b.w;
        ((float4*)dst)[i] = a;
    }
}

// ---------------- layer-1 aggregation: gathers Y directly (dual view, half-warp each) --
__global__ __launch_bounds__(256) void spmm1_kernel(
    const float* __restrict__ Y, float* __restrict__ Pout,
    const float* __restrict__ b, const float* __restrict__ a, int n)
{
    int gw = (blockIdx.x * blockDim.x + threadIdx.x) >> 5;
    int lane = threadIdx.x & 31;
    if (gw >= n) return;
    int half = lane >> 4;        // 0: view1 (Y[s]), 1: view2 (Y[perm[s]])
    int l = lane & 15;

    int beg = g_rowptr[gw], end = g_rowptr[gw + 1];
    float2 acc0 = {0.f, 0.f}, acc1 = {0.f, 0.f}, acc2 = {0.f, 0.f};

    int e = beg;
    for (; e + 1 < end; e += 2) {
        int2 sp0 = g_col2[e], sp1 = g_col2[e + 1];
        float ns0 = g_norm_out[sp0.x], ns1 = g_norm_out[sp1.x];
        int s0 = half ? sp0.y : sp0.x;
        int s1 = half ? sp1.y : sp1.x;
        const float2* h0 = (const float2*)(Y + (size_t)s0 * HDIM);
        const float2* h1 = (const float2*)(Y + (size_t)s1 * HDIM);
        float2 u0 = h0[l], u1 = h0[l + 16], u2 = h0[l + 32];
        float2 v0 = h1[l], v1 = h1[l + 16], v2 = h1[l + 32];
        acc0.x += ns0 * u0.x + ns1 * v0.x; acc0.y += ns0 * u0.y + ns1 * v0.y;
        acc1.x += ns0 * u1.x + ns1 * v1.x; acc1.y += ns0 * u1.y + ns1 * v1.y;
        acc2.x += ns0 * u2.x + ns1 * v2.x; acc2.y += ns0 * u2.y + ns1 * v2.y;
    }
    if (e < end) {
        int2 sp0 = g_col2[e];
        float ns0 = g_norm_out[sp0.x];
        int s0 = half ? sp0.y : sp0.x;
        const float2* h0 = (const float2*)(Y + (size_t)s0 * HDIM);
        float2 u0 = h0[l], u1 = h0[l + 16], u2 = h0[l + 32];
        acc0.x += ns0 * u0.x; acc0.y += ns0 * u0.y;
        acc1.x += ns0 * u1.x; acc1.y += ns0 * u1.y;
        acc2.x += ns0 * u2.x; acc2.y += ns0 * u2.y;
    }

    float ni = g_norm_in[gw];
    float2* po = (float2*)(Pout + (size_t)gw * HDIM2);

    #pragma unroll
    for (int j = 0; j < 3; j++) {
        int idx = l + 16 * j;
        int c0 = 2 * idx;
        float2 acc = (j == 0) ? acc0 : (j == 1) ? acc1 : acc2;
        float h0 = acc.x * ni + b[c0];
        float h1 = acc.y * ni + b[c0 + 1];
        float z0 = (h0 >= 0.f) ? h0 : a[c0] * h0;
        float z1 = (h1 >= 0.f) ? h1 : a[c0 + 1] * h1;
        po[half * 48 + idx] = make_float2(z0, z1);
    }
}

// ---------------- layer-2 aggregation + PReLU + fused projection row-sum ---------------
__global__ __launch_bounds__(256) void spmm2_kernel(
    const float* __restrict__ Hin,
    const float* __restrict__ b, const float* __restrict__ a,
    float* __restrict__ out, int n)
{
    int gw = (blockIdx.x * blockDim.x + threadIdx.x) >> 5;
    int lane = threadIdx.x & 31;
    if (gw >= n) return;

    int beg = g_rowptr[gw], end = g_rowptr[gw + 1];
    float2 acc0 = {0.f, 0.f}, acc1 = {0.f, 0.f}, acc2 = {0.f, 0.f};

    int e = beg;
    for (; e + 1 < end; e += 2) {
        int s0 = g_col2[e].x, s1 = g_col2[e + 1].x;
        const float2* h0 = (const float2*)(Hin + (size_t)s0 * HDIM2);
        const float2* h1 = (const float2*)(Hin + (size_t)s1 * HDIM2);
        float2 u0 = h0[lane], u1 = h0[lane + 32], u2 = h0[lane + 64];
        float2 v0 = h1[lane], v1 = h1[lane + 32], v2 = h1[lane + 64];
        acc0.x += u0.x + v0.x; acc0.y += u0.y + v0.y;
        acc1.x += u1.x + v1.x; acc1.y += u1.y + v1.y;
        acc2.x += u2.x + v2.x; acc2.y += u2.y + v2.y;
    }
    if (e < end) {
        int s0 = g_col2[e].x;
        const float2* h0 = (const float2*)(Hin + (size_t)s0 * HDIM2);
        float2 u0 = h0[lane], u1 = h0[lane + 32], u2 = h0[lane + 64];
        acc0.x += u0.x; acc0.y += u0.y;
        acc1.x += u1.x; acc1.y += u1.y;
        acc2.x += u2.x; acc2.y += u2.y;
    }

    float ni = g_norm_in[gw];
    float s1 = 0.f, s2 = 0.f;

    #pragma unroll
    for (int j = 0; j < 3; j++) {
        int idx = lane + 32 * j;
        float2 acc = (j == 0) ? acc0 : (j == 1) ? acc1 : acc2;
        int v = idx >= 48;
        int c0 = 2 * idx - 96 * v;
        float h0 = acc.x * ni + b[c0];
        float h1 = acc.y * ni + b[c0 + 1];
        float z0 = (h0 >= 0.f) ? h0 : a[c0] * h0;
        float z1 = (h1 >= 0.f) ? h1 : a[c0 + 1] * h1;
        float contrib = z0 * g_wsum[c0] + z1 * g_wsum[c0 + 1];
        if (v) s2 += contrib; else s1 += contrib;
    }

    #pragma unroll
    for (int off = 16; off > 0; off >>= 1) {
        s1 += __shfl_xor_sync(0xffffffff, s1, off);
        s2 += __shfl_xor_sync(0xffffffff, s2, off);
    }
    if (lane == 0) {
        out[gw]     = s1 + g_bmsum;
        out[n + gw] = s2 + g_bmsum;
    }
}

// ---------------- launch ----------------
extern "C" void kernel_launch(void* const* d_in, const int* in_sizes, int n_in,
                              void* d_out, int out_size) {
    const float* x   = (const float*)d_in[0];
    const int*   src = (const int*)  d_in[1];
    const int*   dst = (const int*)  d_in[2];
    const int*   perm= (const int*)  d_in[3];
    const float* W1  = (const float*)d_in[4];
    const float* b1  = (const float*)d_in[5];
    const float* a1  = (const float*)d_in[6];
    const float* W2  = (const float*)d_in[7];
    const float* b2  = (const float*)d_in[8];
    const float* a2  = (const float*)d_in[9];
    const float* Wm  = (const float*)d_in[10];
    const float* bm  = (const float*)d_in[11];
    float* out = (float*)d_out;

    int E = in_sizes[1];
    int n = in_sizes[3];
    int F = in_sizes[0] / n;

    float *pY, *pHB, *pP, *pNormOut;
    cudaGetSymbolAddress((void**)&pY, g_Y);
    cudaGetSymbolAddress((void**)&pHB, g_HB);
    cudaGetSymbolAddress((void**)&pP, g_P);
    cudaGetSymbolAddress((void**)&pNormOut, g_norm_out);

    int nTiles = (n + 127) / 128;

    zero_kernel<<<(n + 255) / 256, 256>>>(n);
    degree_kernel<<<(E + 255) / 256, 256>>>(src, dst, E);
    scan_kernel<<<1, 1024>>>(n, Wm, bm);
    // Y = X @ W1, split-K=2 (y=0: K[0,256) -> Y; y=1: K[256,F) -> HB scratch)
    gemm96_kernel<<<dim3(nTiles, 2), 256>>>(x, F, W1, pY, pHB, HDIM, nullptr, n, F, 256);
    add_kernel<<<(n * HDIM / 4 + 255) / 256, 256>>>(pY, pHB, n * HDIM / 4);
    fill_kernel<<<(E + 255) / 256, 256>>>(src, dst, perm, E);
    // layer-1 aggregation (dual view, direct gather from Y) + PReLU
    spmm1_kernel<<<(n + 7) / 8, 256>>>(pY, pP, b1, a1, n);
    // layer-2 GEMMs, both views in one launch, norm_out fused in epilogue
    gemm96_kernel<<<dim3(nTiles, 2), 256>>>(pP, HDIM2, W2, pHB, nullptr, HDIM2, pNormOut, n, HDIM, 0);
    // layer-2 aggregation + PReLU + fused projection row-sum
    spmm2_kernel<<<(n + 7) / 8, 256>>>(pHB, b2, a2, out, n);
}